// round 13
// baseline (speedup 1.0000x reference)
#include <cuda_runtime.h>
#include <cuda_bf16.h>

// ---------------- problem constants (fixed by the dataset) ----------------
#define NN    50016      // nodes (padded)
#define EE    800000     // edges (self loops handled analytically)
#define FIN   256        // input features
#define D1    128        // HEADS*HID
#define NEG   0.2f       // leaky_relu slope

// ---------------- scratch (static __device__ — no allocs allowed) ----------
__device__ __align__(16) float g_h  [(size_t)NN * D1];   // h = in @ W (per layer)
__device__ __align__(16) float g_hid[(size_t)NN * D1];   // layer-1 output after ELU
__device__ __align__(16) float g_as [NN * 4];            // alpha_src per node/head
__device__ __align__(16) float g_ad [NN * 4];            // alpha_dst per node/head
__device__ int g_deg[NN];        // in-degree histogram (memset to 0 per launch)
__device__ int g_off[NN + 1];    // CSR row offsets (by dst)
__device__ int g_cur[NN];        // scatter cursors
__device__ int g_eidx[EE];       // CSR column indices (src node per slot)

__device__ __forceinline__ float lrelu(float x) { return x >= 0.f ? x : NEG * x; }

__device__ __forceinline__ float bf16_hi(float x) {
    return __bfloat162float(__float2bfloat16(x));   // rn
}
// pack (k even, k odd) floats into one bf16x2 word; low half = even k
__device__ __forceinline__ unsigned pack_bf2(float klo, float khi) {
    unsigned r;
    asm("cvt.rn.bf16x2.f32 %0, %1, %2;" : "=r"(r) : "f"(khi), "f"(klo));
    return r;
}
__device__ __forceinline__ void mma16(float4& d,
                                      unsigned a0, unsigned a1, unsigned a2, unsigned a3,
                                      unsigned b0, unsigned b1) {
    asm volatile(
        "mma.sync.aligned.m16n8k16.row.col.f32.bf16.bf16.f32 "
        "{%0,%1,%2,%3}, {%4,%5,%6,%7}, {%8,%9}, {%0,%1,%2,%3};"
        : "+f"(d.x), "+f"(d.y), "+f"(d.z), "+f"(d.w)
        : "r"(a0), "r"(a1), "r"(a2), "r"(a3), "r"(b0), "r"(b1));
}

// ================= CSR build (once per launch; graph shared by both layers) =
__global__ void csr_hist(const int* __restrict__ ei, int E) {
    int e = blockIdx.x * blockDim.x + threadIdx.x;
    if (e < E) atomicAdd(&g_deg[ei[E + e]], 1);
}
// single-block exclusive scan over n (<=50000) degree counts
__global__ void csr_scan(int n) {
    __shared__ int ssum[1024];
    int t = threadIdx.x;
    int CH = (n + 1023) / 1024;
    int beg = t * CH, end = min(beg + CH, n);
    if (beg > n) beg = n;
    int s = 0;
    for (int i = beg; i < end; i++) s += g_deg[i];
    ssum[t] = s;
    __syncthreads();
    for (int off = 1; off < 1024; off <<= 1) {
        int v = (t >= off) ? ssum[t - off] : 0;
        __syncthreads();
        ssum[t] += v;
        __syncthreads();
    }
    int run = (t == 0) ? 0 : ssum[t - 1];
    for (int i = beg; i < end; i++) {
        int d = g_deg[i];
        g_off[i] = run;
        g_cur[i] = run;
        run += d;
    }
    if (t == 1023) g_off[n] = run;
}
__global__ void csr_scatter(const int* __restrict__ ei, int E) {
    int e = blockIdx.x * blockDim.x + threadIdx.x;
    if (e >= E) return;
    int s = ei[e], d = ei[E + e];
    int pos = atomicAdd(&g_cur[d], 1);
    g_eidx[pos] = s;
}

// ------- 3xBF16 tensor-core GEMM: g_h[M,128] = A[M,K] @ B[K,128] -----------
// 64x128 block tile, 8 warps (2x4), each warp 32x32 as 2x4 m16n8k16 tiles.
// Ootomo bf16x3: a = hi + lo (both bf16); D += Ah*Bh + Ah*Bl + Al*Bh.
// Smem (uint = bf16x2 packed along K, kword = k/2):
//   A: [row][kword] stride 12;  B: [col][kword] stride 12.
//   Fragment pattern addr = 12*gid + tig -> all 32 banks distinct.
__global__ void __launch_bounds__(256, 3)
gemm_bf16x3(const float* __restrict__ Ain, const float* __restrict__ B,
            int M, int K, int useHid) {
    const float* A = useHid ? (const float*)g_hid : Ain;
    __shared__ unsigned Ahm[64 * 12], Alm[64 * 12];    // 64 rows x 8 kwords (+pad)
    __shared__ unsigned Bhm[128 * 12], Blm[128 * 12];  // 128 cols x 8 kwords (+pad)
    const int tid  = threadIdx.x;
    const int lane = tid & 31;
    const int wid  = tid >> 5;
    const int wrow = (wid >> 2) * 32;   // 0 or 32
    const int wcol = (wid & 3) * 32;    // 0,32,64,96
    const int block_row = blockIdx.x * 64;
    const int gid = lane >> 2;          // group id 0..7
    const int tig = lane & 3;           // thread in group 0..3

    float4 acc[2][4];
#pragma unroll
    for (int mr = 0; mr < 2; mr++)
#pragma unroll
        for (int nc = 0; nc < 4; nc++) acc[mr][nc] = make_float4(0.f, 0.f, 0.f, 0.f);

    for (int k0 = 0; k0 < K; k0 += 16) {
        // ---- A tile: 64 rows x 16 k. One float4 per thread -> 2 hi + 2 lo words.
        {
            int row  = tid >> 2;
            int k4   = (tid & 3) << 2;          // 0,4,8,12
            int grow = block_row + row;
            float4 v = make_float4(0.f, 0.f, 0.f, 0.f);
            if (grow < M) v = *(const float4*)&A[(size_t)grow * K + k0 + k4];
            float hx = bf16_hi(v.x), hy = bf16_hi(v.y);
            float hz = bf16_hi(v.z), hw = bf16_hi(v.w);
            int w0 = row * 12 + (k4 >> 1);      // kword index
            Ahm[w0]     = pack_bf2(hx, hy);
            Ahm[w0 + 1] = pack_bf2(hz, hw);
            Alm[w0]     = pack_bf2(v.x - hx, v.y - hy);
            Alm[w0 + 1] = pack_bf2(v.z - hz, v.w - hw);
        }
        // ---- B tile: 16 k x 128 cols. Each thread: one kpair x 4 cols.
        {
            int kp = tid >> 5;                  // kpair 0..7
            int c4 = (tid & 31) << 2;           // col group
            float4 v0 = *(const float4*)&B[(size_t)(k0 + 2 * kp) * 128 + c4];
            float4 v1 = *(const float4*)&B[(size_t)(k0 + 2 * kp + 1) * 128 + c4];
            float h0x = bf16_hi(v0.x), h1x = bf16_hi(v1.x);
            float h0y = bf16_hi(v0.y), h1y = bf16_hi(v1.y);
            float h0z = bf16_hi(v0.z), h1z = bf16_hi(v1.z);
            float h0w = bf16_hi(v0.w), h1w = bf16_hi(v1.w);
            Bhm[(c4 + 0) * 12 + kp] = pack_bf2(h0x, h1x);
            Bhm[(c4 + 1) * 12 + kp] = pack_bf2(h0y, h1y);
            Bhm[(c4 + 2) * 12 + kp] = pack_bf2(h0z, h1z);
            Bhm[(c4 + 3) * 12 + kp] = pack_bf2(h0w, h1w);
            Blm[(c4 + 0) * 12 + kp] = pack_bf2(v0.x - h0x, v1.x - h1x);
            Blm[(c4 + 1) * 12 + kp] = pack_bf2(v0.y - h0y, v1.y - h1y);
            Blm[(c4 + 2) * 12 + kp] = pack_bf2(v0.z - h0z, v1.z - h1z);
            Blm[(c4 + 3) * 12 + kp] = pack_bf2(v0.w - h0w, v1.w - h1w);
        }
        __syncthreads();
        {
            unsigned ah[2][4], al[2][4], bh[4][2], bl[4][2];
#pragma unroll
            for (int mr = 0; mr < 2; mr++) {
                int r0 = wrow + mr * 16 + gid;
                ah[mr][0] = Ahm[r0 * 12 + tig];
                ah[mr][1] = Ahm[(r0 + 8) * 12 + tig];
                ah[mr][2] = Ahm[r0 * 12 + 4 + tig];
                ah[mr][3] = Ahm[(r0 + 8) * 12 + 4 + tig];
                al[mr][0] = Alm[r0 * 12 + tig];
                al[mr][1] = Alm[(r0 + 8) * 12 + tig];
                al[mr][2] = Alm[r0 * 12 + 4 + tig];
                al[mr][3] = Alm[(r0 + 8) * 12 + 4 + tig];
            }
#pragma unroll
            for (int nc = 0; nc < 4; nc++) {
                int col = wcol + nc * 8 + gid;
                bh[nc][0] = Bhm[col * 12 + tig];
                bh[nc][1] = Bhm[col * 12 + 4 + tig];
                bl[nc][0] = Blm[col * 12 + tig];
                bl[nc][1] = Blm[col * 12 + 4 + tig];
            }
#pragma unroll
            for (int mr = 0; mr < 2; mr++)
#pragma unroll
                for (int nc = 0; nc < 4; nc++) {
                    mma16(acc[mr][nc], ah[mr][0], ah[mr][1], ah[mr][2], ah[mr][3],
                          bh[nc][0], bh[nc][1]);
                    mma16(acc[mr][nc], ah[mr][0], ah[mr][1], ah[mr][2], ah[mr][3],
                          bl[nc][0], bl[nc][1]);
                    mma16(acc[mr][nc], al[mr][0], al[mr][1], al[mr][2], al[mr][3],
                          bh[nc][0], bh[nc][1]);
                }
        }
        __syncthreads();
    }
    // epilogue: c0/c1 -> (row, col..col+1), c2/c3 -> (row+8, ...)
#pragma unroll
    for (int mr = 0; mr < 2; mr++) {
        int r0 = block_row + wrow + mr * 16 + gid;
#pragma unroll
        for (int nc = 0; nc < 4; nc++) {
            int col = wcol + nc * 8 + 2 * tig;
            if (r0 < M)
                *(float2*)&g_h[(size_t)r0 * 128 + col] =
                    make_float2(acc[mr][nc].x, acc[mr][nc].y);
            if (r0 + 8 < M)
                *(float2*)&g_h[(size_t)(r0 + 8) * 128 + col] =
                    make_float2(acc[mr][nc].z, acc[mr][nc].w);
        }
    }
}

// ---------------- per-node alphas (warp per node) ---------------------------
__global__ void node_prep(const float* __restrict__ asrc,
                          const float* __restrict__ adst, int n) {
    int node = (blockIdx.x * blockDim.x + threadIdx.x) >> 5;
    int lane = threadIdx.x & 31;
    if (node >= n) return;
    int head = lane >> 3, sub = lane & 7;
    float4 hv = __ldg((const float4*)&g_h[(size_t)node * 128 + lane * 4]);
    float4 av = __ldg((const float4*)&asrc[head * 32 + sub * 4]);
    float4 dv = __ldg((const float4*)&adst[head * 32 + sub * 4]);
    float ps = hv.x * av.x + hv.y * av.y + hv.z * av.z + hv.w * av.w;
    float pd = hv.x * dv.x + hv.y * dv.y + hv.z * dv.z + hv.w * dv.w;
#pragma unroll
    for (int off = 4; off; off >>= 1) {
        ps += __shfl_xor_sync(0xffffffffu, ps, off);
        pd += __shfl_xor_sync(0xffffffffu, pd, off);
    }
    if (sub == 0) {
        g_as[node * 4 + head] = ps;
        g_ad[node * 4 + head] = pd;
    }
}

// ---------------- fused gather-aggregate (warp per dst node) ----------------
// Single edge pass: bare exp (logits O(1), overflow impossible), denom +
// numerator in registers, self loop analytic, normalize, bias, optional ELU.
__global__ void node_aggregate(const float* __restrict__ bias,
                               float* __restrict__ out, int n, int toHidWithElu) {
    int node = (blockIdx.x * blockDim.x + threadIdx.x) >> 5;
    int lane = threadIdx.x & 31;
    if (node >= n) return;
    int head = lane >> 3;
    int beg = g_off[node], end = g_off[node + 1];

    float4 nas4 = __ldg((const float4*)&g_as[node * 4]);
    float4 nad4 = __ldg((const float4*)&g_ad[node * 4]);
    float adh = head == 0 ? nad4.x : head == 1 ? nad4.y : head == 2 ? nad4.z : nad4.w;
    float ash = head == 0 ? nas4.x : head == 1 ? nas4.y : head == 2 ? nas4.z : nas4.w;

    float ax = 0.f, ay = 0.f, az = 0.f, aw = 0.f, den = 0.f;

    for (int j0 = beg; j0 < end; j0 += 32) {
        int cnt = end - j0;
        if (cnt > 32) cnt = 32;
        int sl = 0;
        if (lane < cnt) sl = __ldg(&g_eidx[j0 + lane]);   // coalesced
        int k = 0;
#pragma unroll 1
        for (; k + 4 <= cnt; k += 4) {
            int s0 = __shfl_sync(0xffffffffu, sl, k);
            int s1 = __shfl_sync(0xffffffffu, sl, k + 1);
            int s2 = __shfl_sync(0xffffffffu, sl, k + 2);
            int s3 = __shfl_sync(0xffffffffu, sl, k + 3);
            float a0 = __ldg(&g_as[s0 * 4 + head]);
            float a1 = __ldg(&g_as[s1 * 4 + head]);
            float a2 = __ldg(&g_as[s2 * 4 + head]);
            float a3 = __ldg(&g_as[s3 * 4 + head]);
            float4 h0 = __ldg((const float4*)&g_h[(size_t)s0 * 128 + lane * 4]);
            float4 h1 = __ldg((const float4*)&g_h[(size_t)s1 * 128 + lane * 4]);
            float4 h2 = __ldg((const float4*)&g_h[(size_t)s2 * 128 + lane * 4]);
            float4 h3 = __ldg((const float4*)&g_h[(size_t)s3 * 128 + lane * 4]);
            float e0 = __expf(lrelu(a0 + adh));
            float e1 = __expf(lrelu(a1 + adh));
            float e2 = __expf(lrelu(a2 + adh));
            float e3 = __expf(lrelu(a3 + adh));
            den += (e0 + e1) + (e2 + e3);
            ax += e0 * h0.x + e1 * h1.x + e2 * h2.x + e3 * h3.x;
            ay += e0 * h0.y + e1 * h1.y + e2 * h2.y + e3 * h3.y;
            az += e0 * h0.z + e1 * h1.z + e2 * h2.z + e3 * h3.z;
            aw += e0 * h0.w + e1 * h1.w + e2 * h2.w + e3 * h3.w;
        }
        for (; k < cnt; k++) {
            int s = __shfl_sync(0xffffffffu, sl, k);
            float a  = __ldg(&g_as[s * 4 + head]);
            float4 hv = __ldg((const float4*)&g_h[(size_t)s * 128 + lane * 4]);
            float ev = __expf(lrelu(a + adh));
            den += ev;
            ax += ev * hv.x; ay += ev * hv.y; az += ev * hv.z; aw += ev * hv.w;
        }
    }
    // self loop (every node has exactly one)
    float evs = __expf(lrelu(ash + adh));
    den += evs;
    {
        float4 hv = __ldg((const float4*)&g_h[(size_t)node * 128 + lane * 4]);
        ax += evs * hv.x; ay += evs * hv.y; az += evs * hv.z; aw += evs * hv.w;
    }
    float inv = 1.f / (den + 1e-16f);
    float4 bv = __ldg((const float4*)&bias[lane * 4]);
    float4 o;
    o.x = ax * inv + bv.x;
    o.y = ay * inv + bv.y;
    o.z = az * inv + bv.z;
    o.w = aw * inv + bv.w;
    if (toHidWithElu) {
        o.x = o.x > 0.f ? o.x : expm1f(o.x);
        o.y = o.y > 0.f ? o.y : expm1f(o.y);
        o.z = o.z > 0.f ? o.z : expm1f(o.z);
        o.w = o.w > 0.f ? o.w : expm1f(o.w);
        *(float4*)&g_hid[(size_t)node * 128 + lane * 4] = o;
    } else {
        *(float4*)&out[(size_t)node * 128 + lane * 4] = o;
    }
}

// ---------------- launch ----------------------------------------------------
extern "C" void kernel_launch(void* const* d_in, const int* in_sizes, int n_in,
                              void* d_out, int out_size) {
    const float* x   = (const float*)d_in[0];
    const int*   ei  = (const int*)d_in[1];   // int32 (JAX x64 disabled)
    const float* W1  = (const float*)d_in[2];
    const float* as1 = (const float*)d_in[3];
    const float* ad1 = (const float*)d_in[4];
    const float* b1  = (const float*)d_in[5];
    const float* W2  = (const float*)d_in[6];
    const float* as2 = (const float*)d_in[7];
    const float* ad2 = (const float*)d_in[8];
    const float* b2  = (const float*)d_in[9];
    float* out = (float*)d_out;

    const int E = in_sizes[1] / 2;          // 800000
    const int n = in_sizes[0] / FIN;        // 50000

    const int edgeBlocks = (E + 255) / 256;
    const int gemmBlocks = (n + 63) / 64;
    const int warpBlocks = (n * 32 + 255) / 256;   // warp-per-node kernels

    // ---- CSR build (shared by both layers) ----
    void* degPtr = nullptr;
    cudaGetSymbolAddress(&degPtr, g_deg);               // constant symbol address
    cudaMemsetAsync(degPtr, 0, (size_t)n * sizeof(int), 0);   // capturable memset node
    csr_hist<<<edgeBlocks, 256>>>(ei, E);
    csr_scan<<<1, 1024>>>(n);
    csr_scatter<<<edgeBlocks, 256>>>(ei, E);

    // ---- layer 1 ----
    gemm_bf16x3<<<gemmBlocks, 256>>>(x, W1, n, FIN, 0);
    node_prep<<<warpBlocks, 256>>>(as1, ad1, n);
    node_aggregate<<<warpBlocks, 256>>>(b1, out, n, 1);   // -> g_hid with ELU

    // ---- layer 2 ----
    gemm_bf16x3<<<gemmBlocks, 256>>>(x, W2, n, D1, 1);    // A = g_hid
    node_prep<<<warpBlocks, 256>>>(as2, ad2, n);
    node_aggregate<<<warpBlocks, 256>>>(b2, out, n, 0);   // -> d_out
}

// round 14
// speedup vs baseline: 1.2113x; 1.2113x over previous
#include <cuda_runtime.h>
#include <cuda_bf16.h>

// ---------------- problem constants (fixed by the dataset) ----------------
#define NN    50016      // nodes (padded)
#define EE    800000     // edges (self loops handled analytically)
#define FIN   256        // input features
#define D1    128        // HEADS*HID
#define NEG   0.2f       // leaky_relu slope

// ---------------- scratch (static __device__ — no allocs allowed) ----------
__device__ __align__(16) float g_h  [(size_t)NN * D1];   // h = in @ W (per layer)
__device__ __align__(16) float g_hid[(size_t)NN * D1];   // layer-1 output after ELU
__device__ __align__(16) float g_as [NN * 4];            // alpha_src per node/head
__device__ __align__(16) float g_ad [NN * 4];            // alpha_dst per node/head
__device__ int g_deg[NN];        // in-degree histogram (memset to 0 per launch)
__device__ int g_off[NN + 1];    // CSR row offsets (by dst)
__device__ int g_cur[NN];        // scatter cursors
__device__ int g_eidx[EE];       // CSR column indices (src node per slot)

__device__ __forceinline__ float lrelu(float x) { return x >= 0.f ? x : NEG * x; }

__device__ __forceinline__ float bf16_hi(float x) {
    return __bfloat162float(__float2bfloat16(x));   // rn
}
// pack (k even, k odd) floats into one bf16x2 word; low half = even k
__device__ __forceinline__ unsigned pack_bf2(float klo, float khi) {
    unsigned r;
    asm("cvt.rn.bf16x2.f32 %0, %1, %2;" : "=r"(r) : "f"(khi), "f"(klo));
    return r;
}
__device__ __forceinline__ void mma16(float4& d,
                                      unsigned a0, unsigned a1, unsigned a2, unsigned a3,
                                      unsigned b0, unsigned b1) {
    asm volatile(
        "mma.sync.aligned.m16n8k16.row.col.f32.bf16.bf16.f32 "
        "{%0,%1,%2,%3}, {%4,%5,%6,%7}, {%8,%9}, {%0,%1,%2,%3};"
        : "+f"(d.x), "+f"(d.y), "+f"(d.z), "+f"(d.w)
        : "r"(a0), "r"(a1), "r"(a2), "r"(a3), "r"(b0), "r"(b1));
}

// ================= CSR build (once per launch; graph shared by both layers) =
__global__ void csr_hist(const int* __restrict__ ei, int E) {
    int e = blockIdx.x * blockDim.x + threadIdx.x;
    if (e < E) atomicAdd(&g_deg[ei[E + e]], 1);
}
// single-block exclusive scan over n (<=50000) degree counts
__global__ void csr_scan(int n) {
    __shared__ int ssum[1024];
    int t = threadIdx.x;
    int CH = (n + 1023) / 1024;
    int beg = t * CH, end = min(beg + CH, n);
    if (beg > n) beg = n;
    int s = 0;
    for (int i = beg; i < end; i++) s += g_deg[i];
    ssum[t] = s;
    __syncthreads();
    for (int off = 1; off < 1024; off <<= 1) {
        int v = (t >= off) ? ssum[t - off] : 0;
        __syncthreads();
        ssum[t] += v;
        __syncthreads();
    }
    int run = (t == 0) ? 0 : ssum[t - 1];
    for (int i = beg; i < end; i++) {
        int d = g_deg[i];
        g_off[i] = run;
        g_cur[i] = run;
        run += d;
    }
    if (t == 1023) g_off[n] = run;
}
__global__ void csr_scatter(const int* __restrict__ ei, int E) {
    int e = blockIdx.x * blockDim.x + threadIdx.x;
    if (e >= E) return;
    int s = ei[e], d = ei[E + e];
    int pos = atomicAdd(&g_cur[d], 1);
    g_eidx[pos] = s;
}

// ------- 3xBF16 tensor-core GEMM: g_h[M,128] = A[M,K] @ B[K,128] -----------
// 64x128 block tile, 8 warps (2x4), each warp 32x32 as 2x4 m16n8k16 tiles.
// Ootomo bf16x3: a = hi + lo (both bf16); D += Ah*Bh + Ah*Bl + Al*Bh.
// Smem layout (uint2 = (hi,lo) bf16x2 pair, indexed [kword][row/col]):
//   A: stride 76 uint2 -> frag-load banks 24*tig+2*gid, all distinct.
//   B: stride 140 uint2 -> frag-load banks 24*tig+16*nc+2*gid, all distinct.
//   B stores are per-thread consecutive (2x uint4) -> bandwidth-optimal.
__global__ void __launch_bounds__(256, 3)
gemm_bf16x3(const float* __restrict__ Ain, const float* __restrict__ B,
            int M, int K, int useHid) {
    const float* A = useHid ? (const float*)g_hid : Ain;
    __shared__ uint2 AHL[8 * 76];    // [kword][row],  8 kwords x 64 rows (+pad)
    __shared__ uint2 BHL[8 * 140];   // [kword][col],  8 kwords x 128 cols (+pad)
    const int tid  = threadIdx.x;
    const int lane = tid & 31;
    const int wid  = tid >> 5;
    const int wrow = (wid >> 2) * 32;   // 0 or 32
    const int wcol = (wid & 3) * 32;    // 0,32,64,96
    const int block_row = blockIdx.x * 64;
    const int gid = lane >> 2;          // group id 0..7
    const int tig = lane & 3;           // thread in group 0..3

    float4 acc[2][4];
#pragma unroll
    for (int mr = 0; mr < 2; mr++)
#pragma unroll
        for (int nc = 0; nc < 4; nc++) acc[mr][nc] = make_float4(0.f, 0.f, 0.f, 0.f);

    for (int k0 = 0; k0 < K; k0 += 16) {
        // ---- A tile: 64 rows x 16 k. One float4 per thread -> 2 kwords.
        {
            int row  = tid >> 2;
            int kw0  = (tid & 3) * 2;           // kword 0,2,4,6
            int grow = block_row + row;
            float4 v = make_float4(0.f, 0.f, 0.f, 0.f);
            if (grow < M) v = *(const float4*)&A[(size_t)grow * K + k0 + kw0 * 2];
            float hx = bf16_hi(v.x), hy = bf16_hi(v.y);
            float hz = bf16_hi(v.z), hw = bf16_hi(v.w);
            AHL[kw0 * 76 + row]       = make_uint2(pack_bf2(hx, hy),
                                                   pack_bf2(v.x - hx, v.y - hy));
            AHL[(kw0 + 1) * 76 + row] = make_uint2(pack_bf2(hz, hw),
                                                   pack_bf2(v.z - hz, v.w - hw));
        }
        // ---- B tile: 16 k x 128 cols. Each thread: one kpair x 4 cols.
        {
            int kp = tid >> 5;                  // kword 0..7
            int c4 = (tid & 31) << 2;           // col group
            float4 v0 = *(const float4*)&B[(size_t)(k0 + 2 * kp) * 128 + c4];
            float4 v1 = *(const float4*)&B[(size_t)(k0 + 2 * kp + 1) * 128 + c4];
            float h0x = bf16_hi(v0.x), h1x = bf16_hi(v1.x);
            float h0y = bf16_hi(v0.y), h1y = bf16_hi(v1.y);
            float h0z = bf16_hi(v0.z), h1z = bf16_hi(v1.z);
            float h0w = bf16_hi(v0.w), h1w = bf16_hi(v1.w);
            uint2* dst = &BHL[kp * 140 + c4];   // 4 consecutive uint2
            dst[0] = make_uint2(pack_bf2(h0x, h1x), pack_bf2(v0.x - h0x, v1.x - h1x));
            dst[1] = make_uint2(pack_bf2(h0y, h1y), pack_bf2(v0.y - h0y, v1.y - h1y));
            dst[2] = make_uint2(pack_bf2(h0z, h1z), pack_bf2(v0.z - h0z, v1.z - h1z));
            dst[3] = make_uint2(pack_bf2(h0w, h1w), pack_bf2(v0.w - h0w, v1.w - h1w));
        }
        __syncthreads();
        {
            uint2 af[2][4];   // [mr][reg] (hi,lo)
            uint2 bf[4][2];   // [nc][reg]
#pragma unroll
            for (int mr = 0; mr < 2; mr++) {
                int r0 = wrow + mr * 16 + gid;
                af[mr][0] = AHL[tig * 76 + r0];
                af[mr][1] = AHL[tig * 76 + r0 + 8];
                af[mr][2] = AHL[(tig + 4) * 76 + r0];
                af[mr][3] = AHL[(tig + 4) * 76 + r0 + 8];
            }
#pragma unroll
            for (int nc = 0; nc < 4; nc++) {
                int col = wcol + nc * 8 + gid;
                bf[nc][0] = BHL[tig * 140 + col];
                bf[nc][1] = BHL[(tig + 4) * 140 + col];
            }
#pragma unroll
            for (int mr = 0; mr < 2; mr++)
#pragma unroll
                for (int nc = 0; nc < 4; nc++) {
                    mma16(acc[mr][nc], af[mr][0].x, af[mr][1].x, af[mr][2].x, af[mr][3].x,
                          bf[nc][0].x, bf[nc][1].x);
                    mma16(acc[mr][nc], af[mr][0].x, af[mr][1].x, af[mr][2].x, af[mr][3].x,
                          bf[nc][0].y, bf[nc][1].y);
                    mma16(acc[mr][nc], af[mr][0].y, af[mr][1].y, af[mr][2].y, af[mr][3].y,
                          bf[nc][0].x, bf[nc][1].x);
                }
        }
        __syncthreads();
    }
    // epilogue: c0/c1 -> (row, col..col+1), c2/c3 -> (row+8, ...)
#pragma unroll
    for (int mr = 0; mr < 2; mr++) {
        int r0 = block_row + wrow + mr * 16 + gid;
#pragma unroll
        for (int nc = 0; nc < 4; nc++) {
            int col = wcol + nc * 8 + 2 * tig;
            if (r0 < M)
                *(float2*)&g_h[(size_t)r0 * 128 + col] =
                    make_float2(acc[mr][nc].x, acc[mr][nc].y);
            if (r0 + 8 < M)
                *(float2*)&g_h[(size_t)(r0 + 8) * 128 + col] =
                    make_float2(acc[mr][nc].z, acc[mr][nc].w);
        }
    }
}

// ---------------- per-node alphas (warp per node) ---------------------------
__global__ void node_prep(const float* __restrict__ asrc,
                          const float* __restrict__ adst, int n) {
    int node = (blockIdx.x * blockDim.x + threadIdx.x) >> 5;
    int lane = threadIdx.x & 31;
    if (node >= n) return;
    int head = lane >> 3, sub = lane & 7;
    float4 hv = __ldg((const float4*)&g_h[(size_t)node * 128 + lane * 4]);
    float4 av = __ldg((const float4*)&asrc[head * 32 + sub * 4]);
    float4 dv = __ldg((const float4*)&adst[head * 32 + sub * 4]);
    float ps = hv.x * av.x + hv.y * av.y + hv.z * av.z + hv.w * av.w;
    float pd = hv.x * dv.x + hv.y * dv.y + hv.z * dv.z + hv.w * dv.w;
#pragma unroll
    for (int off = 4; off; off >>= 1) {
        ps += __shfl_xor_sync(0xffffffffu, ps, off);
        pd += __shfl_xor_sync(0xffffffffu, pd, off);
    }
    if (sub == 0) {
        g_as[node * 4 + head] = ps;
        g_ad[node * 4 + head] = pd;
    }
}

// ---------------- fused gather-aggregate (warp per dst node) ----------------
// Single edge pass: bare exp (logits O(1), overflow impossible), denom +
// numerator in registers, self loop analytic, normalize, bias, optional ELU.
__global__ void node_aggregate(const float* __restrict__ bias,
                               float* __restrict__ out, int n, int toHidWithElu) {
    int node = (blockIdx.x * blockDim.x + threadIdx.x) >> 5;
    int lane = threadIdx.x & 31;
    if (node >= n) return;
    int head = lane >> 3;
    int beg = g_off[node], end = g_off[node + 1];

    float4 nas4 = __ldg((const float4*)&g_as[node * 4]);
    float4 nad4 = __ldg((const float4*)&g_ad[node * 4]);
    float adh = head == 0 ? nad4.x : head == 1 ? nad4.y : head == 2 ? nad4.z : nad4.w;
    float ash = head == 0 ? nas4.x : head == 1 ? nas4.y : head == 2 ? nas4.z : nas4.w;

    float ax = 0.f, ay = 0.f, az = 0.f, aw = 0.f, den = 0.f;

    for (int j0 = beg; j0 < end; j0 += 32) {
        int cnt = end - j0;
        if (cnt > 32) cnt = 32;
        int sl = 0;
        if (lane < cnt) sl = __ldg(&g_eidx[j0 + lane]);   // coalesced
        int k = 0;
#pragma unroll 1
        for (; k + 4 <= cnt; k += 4) {
            int s0 = __shfl_sync(0xffffffffu, sl, k);
            int s1 = __shfl_sync(0xffffffffu, sl, k + 1);
            int s2 = __shfl_sync(0xffffffffu, sl, k + 2);
            int s3 = __shfl_sync(0xffffffffu, sl, k + 3);
            float a0 = __ldg(&g_as[s0 * 4 + head]);
            float a1 = __ldg(&g_as[s1 * 4 + head]);
            float a2 = __ldg(&g_as[s2 * 4 + head]);
            float a3 = __ldg(&g_as[s3 * 4 + head]);
            float4 h0 = __ldg((const float4*)&g_h[(size_t)s0 * 128 + lane * 4]);
            float4 h1 = __ldg((const float4*)&g_h[(size_t)s1 * 128 + lane * 4]);
            float4 h2 = __ldg((const float4*)&g_h[(size_t)s2 * 128 + lane * 4]);
            float4 h3 = __ldg((const float4*)&g_h[(size_t)s3 * 128 + lane * 4]);
            float e0 = __expf(lrelu(a0 + adh));
            float e1 = __expf(lrelu(a1 + adh));
            float e2 = __expf(lrelu(a2 + adh));
            float e3 = __expf(lrelu(a3 + adh));
            den += (e0 + e1) + (e2 + e3);
            ax += e0 * h0.x + e1 * h1.x + e2 * h2.x + e3 * h3.x;
            ay += e0 * h0.y + e1 * h1.y + e2 * h2.y + e3 * h3.y;
            az += e0 * h0.z + e1 * h1.z + e2 * h2.z + e3 * h3.z;
            aw += e0 * h0.w + e1 * h1.w + e2 * h2.w + e3 * h3.w;
        }
        for (; k < cnt; k++) {
            int s = __shfl_sync(0xffffffffu, sl, k);
            float a  = __ldg(&g_as[s * 4 + head]);
            float4 hv = __ldg((const float4*)&g_h[(size_t)s * 128 + lane * 4]);
            float ev = __expf(lrelu(a + adh));
            den += ev;
            ax += ev * hv.x; ay += ev * hv.y; az += ev * hv.z; aw += ev * hv.w;
        }
    }
    // self loop (every node has exactly one)
    float evs = __expf(lrelu(ash + adh));
    den += evs;
    {
        float4 hv = __ldg((const float4*)&g_h[(size_t)node * 128 + lane * 4]);
        ax += evs * hv.x; ay += evs * hv.y; az += evs * hv.z; aw += evs * hv.w;
    }
    float inv = 1.f / (den + 1e-16f);
    float4 bv = __ldg((const float4*)&bias[lane * 4]);
    float4 o;
    o.x = ax * inv + bv.x;
    o.y = ay * inv + bv.y;
    o.z = az * inv + bv.z;
    o.w = aw * inv + bv.w;
    if (toHidWithElu) {
        o.x = o.x > 0.f ? o.x : expm1f(o.x);
        o.y = o.y > 0.f ? o.y : expm1f(o.y);
        o.z = o.z > 0.f ? o.z : expm1f(o.z);
        o.w = o.w > 0.f ? o.w : expm1f(o.w);
        *(float4*)&g_hid[(size_t)node * 128 + lane * 4] = o;
    } else {
        *(float4*)&out[(size_t)node * 128 + lane * 4] = o;
    }
}

// ---------------- launch ----------------------------------------------------
extern "C" void kernel_launch(void* const* d_in, const int* in_sizes, int n_in,
                              void* d_out, int out_size) {
    const float* x   = (const float*)d_in[0];
    const int*   ei  = (const int*)d_in[1];   // int32 (JAX x64 disabled)
    const float* W1  = (const float*)d_in[2];
    const float* as1 = (const float*)d_in[3];
    const float* ad1 = (const float*)d_in[4];
    const float* b1  = (const float*)d_in[5];
    const float* W2  = (const float*)d_in[6];
    const float* as2 = (const float*)d_in[7];
    const float* ad2 = (const float*)d_in[8];
    const float* b2  = (const float*)d_in[9];
    float* out = (float*)d_out;

    const int E = in_sizes[1] / 2;          // 800000
    const int n = in_sizes[0] / FIN;        // 50000

    const int edgeBlocks = (E + 255) / 256;
    const int gemmBlocks = (n + 63) / 64;
    const int warpBlocks = (n * 32 + 255) / 256;   // warp-per-node kernels

    // ---- CSR build (shared by both layers) ----
    void* degPtr = nullptr;
    cudaGetSymbolAddress(&degPtr, g_deg);               // constant symbol address
    cudaMemsetAsync(degPtr, 0, (size_t)n * sizeof(int), 0);   // capturable memset node
    csr_hist<<<edgeBlocks, 256>>>(ei, E);
    csr_scan<<<1, 1024>>>(n);
    csr_scatter<<<edgeBlocks, 256>>>(ei, E);

    // ---- layer 1 ----
    gemm_bf16x3<<<gemmBlocks, 256>>>(x, W1, n, FIN, 0);
    node_prep<<<warpBlocks, 256>>>(as1, ad1, n);
    node_aggregate<<<warpBlocks, 256>>>(b1, out, n, 1);   // -> g_hid with ELU

    // ---- layer 2 ----
    gemm_bf16x3<<<gemmBlocks, 256>>>(x, W2, n, D1, 1);    // A = g_hid
    node_prep<<<warpBlocks, 256>>>(as2, ad2, n);
    node_aggregate<<<warpBlocks, 256>>>(b2, out, n, 0);   // -> d_out
}

// round 15
// speedup vs baseline: 1.2132x; 1.0015x over previous
#include <cuda_runtime.h>
#include <cuda_bf16.h>

// ---------------- problem constants (fixed by the dataset) ----------------
#define NN    50016      // nodes (padded)
#define EE    800000     // edges (self loops handled analytically)
#define FIN   256        // input features
#define D1    128        // HEADS*HID
#define NEG   0.2f       // leaky_relu slope

// ---------------- scratch (static __device__ — no allocs allowed) ----------
__device__ __align__(16) float g_h  [(size_t)NN * D1];   // h = in @ W (per layer)
__device__ __align__(16) float g_hid[(size_t)NN * D1];   // layer-1 output after ELU
__device__ __align__(16) float g_as [NN * 4];            // alpha_src per node/head
__device__ __align__(16) float g_ad [NN * 4];            // alpha_dst per node/head
__device__ int g_deg[NN];        // in-degree histogram (memset to 0 per launch)
__device__ int g_off[NN + 1];    // CSR row offsets (by dst)
__device__ int g_cur[NN];        // scatter cursors
__device__ int g_eidx[EE];       // CSR column indices (src node per slot)

__device__ __forceinline__ float lrelu(float x) { return x >= 0.f ? x : NEG * x; }

__device__ __forceinline__ float bf16_hi(float x) {
    return __bfloat162float(__float2bfloat16(x));   // rn
}
// pack (k even, k odd) floats into one bf16x2 word; low half = even k
__device__ __forceinline__ unsigned pack_bf2(float klo, float khi) {
    unsigned r;
    asm("cvt.rn.bf16x2.f32 %0, %1, %2;" : "=r"(r) : "f"(khi), "f"(klo));
    return r;
}
__device__ __forceinline__ void mma16(float4& d,
                                      unsigned a0, unsigned a1, unsigned a2, unsigned a3,
                                      unsigned b0, unsigned b1) {
    asm volatile(
        "mma.sync.aligned.m16n8k16.row.col.f32.bf16.bf16.f32 "
        "{%0,%1,%2,%3}, {%4,%5,%6,%7}, {%8,%9}, {%0,%1,%2,%3};"
        : "+f"(d.x), "+f"(d.y), "+f"(d.z), "+f"(d.w)
        : "r"(a0), "r"(a1), "r"(a2), "r"(a3), "r"(b0), "r"(b1));
}

// ================= CSR build (once per launch; graph shared by both layers) =
__global__ void csr_hist(const int* __restrict__ ei, int E) {
    int e = blockIdx.x * blockDim.x + threadIdx.x;
    if (e < E) atomicAdd(&g_deg[ei[E + e]], 1);
}
// single-block exclusive scan over n (<=50000) degree counts
__global__ void csr_scan(int n) {
    __shared__ int ssum[1024];
    int t = threadIdx.x;
    int CH = (n + 1023) / 1024;
    int beg = t * CH, end = min(beg + CH, n);
    if (beg > n) beg = n;
    int s = 0;
    for (int i = beg; i < end; i++) s += g_deg[i];
    ssum[t] = s;
    __syncthreads();
    for (int off = 1; off < 1024; off <<= 1) {
        int v = (t >= off) ? ssum[t - off] : 0;
        __syncthreads();
        ssum[t] += v;
        __syncthreads();
    }
    int run = (t == 0) ? 0 : ssum[t - 1];
    for (int i = beg; i < end; i++) {
        int d = g_deg[i];
        g_off[i] = run;
        g_cur[i] = run;
        run += d;
    }
    if (t == 1023) g_off[n] = run;
}
__global__ void csr_scatter(const int* __restrict__ ei, int E) {
    int e = blockIdx.x * blockDim.x + threadIdx.x;
    if (e >= E) return;
    int s = ei[e], d = ei[E + e];
    int pos = atomicAdd(&g_cur[d], 1);
    g_eidx[pos] = s;
}

// ------- 3xBF16 tensor-core GEMM: g_h[M,128] = A[M,K] @ B[K,128] -----------
// 64x128 block tile, 8 warps (2x4), each warp 32x32 as 2x4 m16n8k16 tiles.
// Ootomo bf16x3: a = hi + lo (both bf16); D += Ah*Bh + Ah*Bl + Al*Bh.
// Smem layout (uint2 = (hi,lo) bf16x2 pair, indexed [kword][row/col]):
//   A: stride 76 uint2 -> frag-load banks 24*tig+2*gid, all distinct.
//   B: stride 140 uint2 -> frag-load banks 24*tig+16*nc+2*gid, all distinct.
//   B stores are per-thread consecutive (2x uint4) -> bandwidth-optimal.
__global__ void __launch_bounds__(256, 3)
gemm_bf16x3(const float* __restrict__ Ain, const float* __restrict__ B,
            int M, int K, int useHid) {
    const float* A = useHid ? (const float*)g_hid : Ain;
    __shared__ uint2 AHL[8 * 76];    // [kword][row],  8 kwords x 64 rows (+pad)
    __shared__ uint2 BHL[8 * 140];   // [kword][col],  8 kwords x 128 cols (+pad)
    const int tid  = threadIdx.x;
    const int lane = tid & 31;
    const int wid  = tid >> 5;
    const int wrow = (wid >> 2) * 32;   // 0 or 32
    const int wcol = (wid & 3) * 32;    // 0,32,64,96
    const int block_row = blockIdx.x * 64;
    const int gid = lane >> 2;          // group id 0..7
    const int tig = lane & 3;           // thread in group 0..3

    float4 acc[2][4];
#pragma unroll
    for (int mr = 0; mr < 2; mr++)
#pragma unroll
        for (int nc = 0; nc < 4; nc++) acc[mr][nc] = make_float4(0.f, 0.f, 0.f, 0.f);

    for (int k0 = 0; k0 < K; k0 += 16) {
        // ---- A tile: 64 rows x 16 k. One float4 per thread -> 2 kwords.
        {
            int row  = tid >> 2;
            int kw0  = (tid & 3) * 2;           // kword 0,2,4,6
            int grow = block_row + row;
            float4 v = make_float4(0.f, 0.f, 0.f, 0.f);
            if (grow < M) v = *(const float4*)&A[(size_t)grow * K + k0 + kw0 * 2];
            float hx = bf16_hi(v.x), hy = bf16_hi(v.y);
            float hz = bf16_hi(v.z), hw = bf16_hi(v.w);
            AHL[kw0 * 76 + row]       = make_uint2(pack_bf2(hx, hy),
                                                   pack_bf2(v.x - hx, v.y - hy));
            AHL[(kw0 + 1) * 76 + row] = make_uint2(pack_bf2(hz, hw),
                                                   pack_bf2(v.z - hz, v.w - hw));
        }
        // ---- B tile: 16 k x 128 cols. Each thread: one kpair x 4 cols.
        {
            int kp = tid >> 5;                  // kword 0..7
            int c4 = (tid & 31) << 2;           // col group
            float4 v0 = *(const float4*)&B[(size_t)(k0 + 2 * kp) * 128 + c4];
            float4 v1 = *(const float4*)&B[(size_t)(k0 + 2 * kp + 1) * 128 + c4];
            float h0x = bf16_hi(v0.x), h1x = bf16_hi(v1.x);
            float h0y = bf16_hi(v0.y), h1y = bf16_hi(v1.y);
            float h0z = bf16_hi(v0.z), h1z = bf16_hi(v1.z);
            float h0w = bf16_hi(v0.w), h1w = bf16_hi(v1.w);
            uint2* dst = &BHL[kp * 140 + c4];   // 4 consecutive uint2
            dst[0] = make_uint2(pack_bf2(h0x, h1x), pack_bf2(v0.x - h0x, v1.x - h1x));
            dst[1] = make_uint2(pack_bf2(h0y, h1y), pack_bf2(v0.y - h0y, v1.y - h1y));
            dst[2] = make_uint2(pack_bf2(h0z, h1z), pack_bf2(v0.z - h0z, v1.z - h1z));
            dst[3] = make_uint2(pack_bf2(h0w, h1w), pack_bf2(v0.w - h0w, v1.w - h1w));
        }
        __syncthreads();
        {
            uint2 af[2][4];   // [mr][reg] (hi,lo)
            uint2 bf[4][2];   // [nc][reg]
#pragma unroll
            for (int mr = 0; mr < 2; mr++) {
                int r0 = wrow + mr * 16 + gid;
                af[mr][0] = AHL[tig * 76 + r0];
                af[mr][1] = AHL[tig * 76 + r0 + 8];
                af[mr][2] = AHL[(tig + 4) * 76 + r0];
                af[mr][3] = AHL[(tig + 4) * 76 + r0 + 8];
            }
#pragma unroll
            for (int nc = 0; nc < 4; nc++) {
                int col = wcol + nc * 8 + gid;
                bf[nc][0] = BHL[tig * 140 + col];
                bf[nc][1] = BHL[(tig + 4) * 140 + col];
            }
#pragma unroll
            for (int mr = 0; mr < 2; mr++)
#pragma unroll
                for (int nc = 0; nc < 4; nc++) {
                    mma16(acc[mr][nc], af[mr][0].x, af[mr][1].x, af[mr][2].x, af[mr][3].x,
                          bf[nc][0].x, bf[nc][1].x);
                    mma16(acc[mr][nc], af[mr][0].x, af[mr][1].x, af[mr][2].x, af[mr][3].x,
                          bf[nc][0].y, bf[nc][1].y);
                    mma16(acc[mr][nc], af[mr][0].y, af[mr][1].y, af[mr][2].y, af[mr][3].y,
                          bf[nc][0].x, bf[nc][1].x);
                }
        }
        __syncthreads();
    }
    // epilogue: c0/c1 -> (row, col..col+1), c2/c3 -> (row+8, ...)
#pragma unroll
    for (int mr = 0; mr < 2; mr++) {
        int r0 = block_row + wrow + mr * 16 + gid;
#pragma unroll
        for (int nc = 0; nc < 4; nc++) {
            int col = wcol + nc * 8 + 2 * tig;
            if (r0 < M)
                *(float2*)&g_h[(size_t)r0 * 128 + col] =
                    make_float2(acc[mr][nc].x, acc[mr][nc].y);
            if (r0 + 8 < M)
                *(float2*)&g_h[(size_t)(r0 + 8) * 128 + col] =
                    make_float2(acc[mr][nc].z, acc[mr][nc].w);
        }
    }
}

// ---------------- per-node alphas (warp per node) ---------------------------
__global__ void node_prep(const float* __restrict__ asrc,
                          const float* __restrict__ adst, int n) {
    int node = (blockIdx.x * blockDim.x + threadIdx.x) >> 5;
    int lane = threadIdx.x & 31;
    if (node >= n) return;
    int head = lane >> 3, sub = lane & 7;
    float4 hv = __ldg((const float4*)&g_h[(size_t)node * 128 + lane * 4]);
    float4 av = __ldg((const float4*)&asrc[head * 32 + sub * 4]);
    float4 dv = __ldg((const float4*)&adst[head * 32 + sub * 4]);
    float ps = hv.x * av.x + hv.y * av.y + hv.z * av.z + hv.w * av.w;
    float pd = hv.x * dv.x + hv.y * dv.y + hv.z * dv.z + hv.w * dv.w;
#pragma unroll
    for (int off = 4; off; off >>= 1) {
        ps += __shfl_xor_sync(0xffffffffu, ps, off);
        pd += __shfl_xor_sync(0xffffffffu, pd, off);
    }
    if (sub == 0) {
        g_as[node * 4 + head] = ps;
        g_ad[node * 4 + head] = pd;
    }
}

// ---------------- fused gather-aggregate (warp per dst node) ----------------
// Single edge pass: bare exp (logits O(1), overflow impossible), denom +
// numerator in registers, self loop analytic, normalize, bias, optional ELU.
__global__ void node_aggregate(const float* __restrict__ bias,
                               float* __restrict__ out, int n, int toHidWithElu) {
    int node = (blockIdx.x * blockDim.x + threadIdx.x) >> 5;
    int lane = threadIdx.x & 31;
    if (node >= n) return;
    int head = lane >> 3;
    int beg = g_off[node], end = g_off[node + 1];

    float4 nas4 = __ldg((const float4*)&g_as[node * 4]);
    float4 nad4 = __ldg((const float4*)&g_ad[node * 4]);
    float adh = head == 0 ? nad4.x : head == 1 ? nad4.y : head == 2 ? nad4.z : nad4.w;
    float ash = head == 0 ? nas4.x : head == 1 ? nas4.y : head == 2 ? nas4.z : nas4.w;

    float ax = 0.f, ay = 0.f, az = 0.f, aw = 0.f, den = 0.f;

    for (int j0 = beg; j0 < end; j0 += 32) {
        int cnt = end - j0;
        if (cnt > 32) cnt = 32;
        int sl = 0;
        if (lane < cnt) sl = __ldg(&g_eidx[j0 + lane]);   // coalesced
        int k = 0;
#pragma unroll 1
        for (; k + 4 <= cnt; k += 4) {
            int s0 = __shfl_sync(0xffffffffu, sl, k);
            int s1 = __shfl_sync(0xffffffffu, sl, k + 1);
            int s2 = __shfl_sync(0xffffffffu, sl, k + 2);
            int s3 = __shfl_sync(0xffffffffu, sl, k + 3);
            float a0 = __ldg(&g_as[s0 * 4 + head]);
            float a1 = __ldg(&g_as[s1 * 4 + head]);
            float a2 = __ldg(&g_as[s2 * 4 + head]);
            float a3 = __ldg(&g_as[s3 * 4 + head]);
            float4 h0 = __ldg((const float4*)&g_h[(size_t)s0 * 128 + lane * 4]);
            float4 h1 = __ldg((const float4*)&g_h[(size_t)s1 * 128 + lane * 4]);
            float4 h2 = __ldg((const float4*)&g_h[(size_t)s2 * 128 + lane * 4]);
            float4 h3 = __ldg((const float4*)&g_h[(size_t)s3 * 128 + lane * 4]);
            float e0 = __expf(lrelu(a0 + adh));
            float e1 = __expf(lrelu(a1 + adh));
            float e2 = __expf(lrelu(a2 + adh));
            float e3 = __expf(lrelu(a3 + adh));
            den += (e0 + e1) + (e2 + e3);
            ax += e0 * h0.x + e1 * h1.x + e2 * h2.x + e3 * h3.x;
            ay += e0 * h0.y + e1 * h1.y + e2 * h2.y + e3 * h3.y;
            az += e0 * h0.z + e1 * h1.z + e2 * h2.z + e3 * h3.z;
            aw += e0 * h0.w + e1 * h1.w + e2 * h2.w + e3 * h3.w;
        }
        for (; k < cnt; k++) {
            int s = __shfl_sync(0xffffffffu, sl, k);
            float a  = __ldg(&g_as[s * 4 + head]);
            float4 hv = __ldg((const float4*)&g_h[(size_t)s * 128 + lane * 4]);
            float ev = __expf(lrelu(a + adh));
            den += ev;
            ax += ev * hv.x; ay += ev * hv.y; az += ev * hv.z; aw += ev * hv.w;
        }
    }
    // self loop (every node has exactly one)
    float evs = __expf(lrelu(ash + adh));
    den += evs;
    {
        float4 hv = __ldg((const float4*)&g_h[(size_t)node * 128 + lane * 4]);
        ax += evs * hv.x; ay += evs * hv.y; az += evs * hv.z; aw += evs * hv.w;
    }
    float inv = 1.f / (den + 1e-16f);
    float4 bv = __ldg((const float4*)&bias[lane * 4]);
    float4 o;
    o.x = ax * inv + bv.x;
    o.y = ay * inv + bv.y;
    o.z = az * inv + bv.z;
    o.w = aw * inv + bv.w;
    if (toHidWithElu) {
        o.x = o.x > 0.f ? o.x : expm1f(o.x);
        o.y = o.y > 0.f ? o.y : expm1f(o.y);
        o.z = o.z > 0.f ? o.z : expm1f(o.z);
        o.w = o.w > 0.f ? o.w : expm1f(o.w);
        *(float4*)&g_hid[(size_t)node * 128 + lane * 4] = o;
    } else {
        *(float4*)&out[(size_t)node * 128 + lane * 4] = o;
    }
}

// ---------------- launch ----------------------------------------------------
extern "C" void kernel_launch(void* const* d_in, const int* in_sizes, int n_in,
                              void* d_out, int out_size) {
    const float* x   = (const float*)d_in[0];
    const int*   ei  = (const int*)d_in[1];   // int32 (JAX x64 disabled)
    const float* W1  = (const float*)d_in[2];
    const float* as1 = (const float*)d_in[3];
    const float* ad1 = (const float*)d_in[4];
    const float* b1  = (const float*)d_in[5];
    const float* W2  = (const float*)d_in[6];
    const float* as2 = (const float*)d_in[7];
    const float* ad2 = (const float*)d_in[8];
    const float* b2  = (const float*)d_in[9];
    float* out = (float*)d_out;

    const int E = in_sizes[1] / 2;          // 800000
    const int n = in_sizes[0] / FIN;        // 50000

    const int edgeBlocks = (E + 255) / 256;
    const int gemmBlocks = (n + 63) / 64;
    const int warpBlocks = (n * 32 + 255) / 256;   // warp-per-node kernels

    // ---- CSR build (shared by both layers) ----
    void* degPtr = nullptr;
    cudaGetSymbolAddress(&degPtr, g_deg);               // constant symbol address
    cudaMemsetAsync(degPtr, 0, (size_t)n * sizeof(int), 0);   // capturable memset node
    csr_hist<<<edgeBlocks, 256>>>(ei, E);
    csr_scan<<<1, 1024>>>(n);
    csr_scatter<<<edgeBlocks, 256>>>(ei, E);

    // ---- layer 1 ----
    gemm_bf16x3<<<gemmBlocks, 256>>>(x, W1, n, FIN, 0);
    node_prep<<<warpBlocks, 256>>>(as1, ad1, n);
    node_aggregate<<<warpBlocks, 256>>>(b1, out, n, 1);   // -> g_hid with ELU

    // ---- layer 2 ----
    gemm_bf16x3<<<gemmBlocks, 256>>>(x, W2, n, D1, 1);    // A = g_hid
    node_prep<<<warpBlocks, 256>>>(as2, ad2, n);
    node_aggregate<<<warpBlocks, 256>>>(b2, out, n, 0);   // -> d_out
}